// round 8
// baseline (speedup 1.0000x reference)
#include <cuda_runtime.h>
#include <cstdint>

#define NP 131072
#define NS 16
#define C  256

// ------------------------------- scratch ----------------------------------
__device__ float g_wt[C * C];          // g_wt[n*C+k] = rna(W1[k*C+n]) (W1a^T, tf32)
__device__ float g_w2t[C * C];         // W2^T
__device__ float g_w1bt[C * C];        // W1b^T
__device__ float g_part[NS * 32 * C];  // per-(seg,sub) partial sums
__device__ float g_y[NS * C];
__device__ float g_z[NS * C];
__device__ float g_bn[2 * C];

// ------------------------------- helpers ----------------------------------
__device__ __forceinline__ float tf32r(float f) {
    unsigned u;
    asm("cvt.rna.tf32.f32 %0, %1;" : "=r"(u) : "f"(f));
    return __uint_as_float(u);
}
__device__ __forceinline__ unsigned tf32u(float f) {
    unsigned u;
    asm("cvt.rna.tf32.f32 %0, %1;" : "=r"(u) : "f"(f));
    return u;
}
__device__ __forceinline__ uint32_t s2u(const void* p) {
    uint32_t a;
    asm("{ .reg .u64 t; cvta.to.shared.u64 t, %1; cvt.u32.u64 %0, t; }" : "=r"(a) : "l"(p));
    return a;
}
__device__ __forceinline__ void cpa16(uint32_t dst, const void* src) {
    asm volatile("cp.async.cg.shared.global [%0], [%1], 16;" :: "r"(dst), "l"(src));
}

// ---------------- K2: ragged segment partial sums (no atomics) -------------
__global__ void k_segsum(const float* __restrict__ x, const int* __restrict__ o) {
    int seg = blockIdx.x >> 5;
    int sub = blockIdx.x & 31;
    int t = threadIdx.x;
    int start = seg ? o[seg - 1] : 0;
    int end = o[seg];
    float acc = 0.f;
    #pragma unroll 4
    for (int r = start + sub; r < end; r += 32)
        acc += x[(size_t)r * C + t];
    g_part[(size_t)blockIdx.x * C + t] = acc;
}

// ---------------- K2b: weight transposes; block (0,0,0) zeroes g_bn -------
__global__ void k_wt(const float* __restrict__ W1, const float* __restrict__ W2) {
    __shared__ float tl[32][33];
    int k0 = blockIdx.x * 32, n0 = blockIdx.y * 32;
    int which = blockIdx.z;
    int tx = threadIdx.x, ty = threadIdx.y;
    if (blockIdx.x == 0 && blockIdx.y == 0 && which == 0) {
        int t = ty * 32 + tx;
        g_bn[t] = 0.f;
        g_bn[t + 256] = 0.f;
    }
    const float* src = (which == 0) ? &W1[(size_t)k0 * C + n0]
                     : (which == 1) ? &W2[(size_t)k0 * C + n0]
                                    : &W1[(size_t)(C + k0) * C + n0];
    #pragma unroll
    for (int i = 0; i < 32; i += 8)
        tl[ty + i][tx] = src[(size_t)(ty + i) * C + tx];
    __syncthreads();
    float* dst = (which == 0) ? g_wt : (which == 1) ? g_w2t : g_w1bt;
    #pragma unroll
    for (int i = 0; i < 32; i += 8) {
        float v = tl[tx][ty + i];
        dst[(size_t)(n0 + ty + i) * C + k0 + tx] = (which == 0) ? tf32r(v) : v;
    }
}

// ---------------- K3a: y = relu(means @ W2 + b2), coalesced W2^T ----------
__global__ __launch_bounds__(256) void k_mlp1(const int* __restrict__ o,
                                              const float* __restrict__ b2) {
    __shared__ float m[C];
    int seg = blockIdx.x >> 5;
    int cb = blockIdx.x & 31;
    int t = threadIdx.x, w = t >> 5, lane = t & 31;
    int start = seg ? o[seg - 1] : 0;
    float inv = 1.f / (float)(o[seg] - start);
    float s = 0.f;
    #pragma unroll
    for (int sub = 0; sub < 32; sub++)
        s += g_part[(size_t)(seg * 32 + sub) * C + t];
    m[t] = s * inv;
    __syncthreads();
    int c = cb * 8 + w;
    const float* wr = &g_w2t[(size_t)c * C];
    float acc = 0.f;
    #pragma unroll
    for (int j = 0; j < 8; j++) {
        int k = lane + 32 * j;
        acc = fmaf(m[k], wr[k], acc);
    }
    #pragma unroll
    for (int off = 16; off; off >>= 1) acc += __shfl_xor_sync(0xffffffffu, acc, off);
    if (lane == 0) g_y[seg * C + c] = fmaxf(acc + b2[c], 0.f);
}

// ---------------- K3b: z = y @ W1b + b1, coalesced W1b^T -------------------
__global__ __launch_bounds__(256) void k_mlp2(const float* __restrict__ b1) {
    __shared__ float y[C];
    int seg = blockIdx.x >> 5;
    int cb = blockIdx.x & 31;
    int t = threadIdx.x, w = t >> 5, lane = t & 31;
    y[t] = g_y[seg * C + t];
    __syncthreads();
    int c = cb * 8 + w;
    const float* wr = &g_w1bt[(size_t)c * C];
    float acc = 0.f;
    #pragma unroll
    for (int j = 0; j < 8; j++) {
        int k = lane + 32 * j;
        acc = fmaf(y[k], wr[k], acc);
    }
    #pragma unroll
    for (int off = 16; off; off >>= 1) acc += __shfl_xor_sync(0xffffffffu, acc, off);
    if (lane == 0) g_z[seg * C + c] = acc + b1[c];
}

// ---------------- K4: tf32 mma.sync GEMM, 64x64 warp tiles ----------------
// 128x128 block tile, 4 warps (2m x 2n), warp tile 64x64, BK=32, 2-stage.
#define BM 128
#define BN 128

__device__ __forceinline__ int sidx(int r, int k) {
    return r * 32 + (k ^ ((r & 7) * 4));
}

__global__ __launch_bounds__(128, 2) void k_mm(const float* __restrict__ x,
                                               const int* __restrict__ o,
                                               float* __restrict__ h) {
    extern __shared__ __align__(128) float smem[];  // 16384 floats = 64KB
    __shared__ int so[NS];
    __shared__ float shbn[256];

    uint32_t sb = s2u(smem);
    int tid = threadIdx.x;                 // 0..127
    int w = tid >> 5, lane = tid & 31;
    int l4 = lane >> 2, lm4 = lane & 3;
    int wm = (w & 1) * 64;
    int wn = (w >> 1) * 64;
    int r0 = blockIdx.y * BM;
    int c0 = blockIdx.x * BN;

    if (tid < NS) so[tid] = o[tid];
    shbn[tid] = 0.f;
    shbn[tid + 128] = 0.f;

    // stage tile kt -> buffer kt&1. Buffer b: A at b*8192, B at b*8192+4096.
    auto stage = [&](int kt) {
        int buf = kt & 1;
        const float* xs = x + (size_t)r0 * C + kt * 32;
        const float* ws = g_wt + (size_t)c0 * C + kt * 32;
        uint32_t ab = sb + buf * 32768;
        uint32_t bb = ab + 16384;
        #pragma unroll
        for (int i = 0; i < 8; i++) {
            int cid = tid + i * 128;        // 1024 chunks of 16B each side
            int row = cid >> 3, c16 = cid & 7;
            uint32_t off = row * 128 + ((c16 * 16) ^ ((row & 7) * 16));
            cpa16(ab + off, xs + (size_t)row * C + c16 * 4);
            cpa16(bb + off, ws + (size_t)row * C + c16 * 4);
        }
        asm volatile("cp.async.commit_group;" ::: "memory");
    };

    float acc[4][8][4] = {};    // [mi][ni][frag]
    stage(0);

    for (int kt = 0; kt < 8; kt++) {
        if (kt < 7) {
            stage(kt + 1);
            asm volatile("cp.async.wait_group 1;" ::: "memory");
        } else {
            asm volatile("cp.async.wait_group 0;" ::: "memory");
        }
        __syncthreads();

        const float* A = smem + (kt & 1) * 8192;
        const float* B = A + 4096;

        #pragma unroll
        for (int ks = 0; ks < 4; ks++) {
            int kb = ks * 8 + lm4;
            unsigned af[4][4];
            unsigned bf[8][2];
            #pragma unroll
            for (int mi = 0; mi < 4; mi++) {
                int m0 = wm + mi * 16 + l4;
                af[mi][0] = tf32u(A[sidx(m0,     kb)]);
                af[mi][1] = tf32u(A[sidx(m0 + 8, kb)]);
                af[mi][2] = tf32u(A[sidx(m0,     kb + 4)]);
                af[mi][3] = tf32u(A[sidx(m0 + 8, kb + 4)]);
            }
            #pragma unroll
            for (int ni = 0; ni < 8; ni++) {
                int n = wn + ni * 8 + l4;
                bf[ni][0] = __float_as_uint(B[sidx(n, kb)]);
                bf[ni][1] = __float_as_uint(B[sidx(n, kb + 4)]);
            }
            #pragma unroll
            for (int mi = 0; mi < 4; mi++)
                #pragma unroll
                for (int ni = 0; ni < 8; ni++)
                    asm volatile(
                        "mma.sync.aligned.m16n8k8.row.col.f32.tf32.tf32.f32 "
                        "{%0,%1,%2,%3},{%4,%5,%6,%7},{%8,%9},{%0,%1,%2,%3};"
                        : "+f"(acc[mi][ni][0]), "+f"(acc[mi][ni][1]),
                          "+f"(acc[mi][ni][2]), "+f"(acc[mi][ni][3])
                        : "r"(af[mi][0]), "r"(af[mi][1]),
                          "r"(af[mi][2]), "r"(af[mi][3]),
                          "r"(bf[ni][0]), "r"(bf[ni][1]));
        }
        __syncthreads();
    }

    // ---- epilogue: + z[seg], write h, fused BN partial sums ----
    float cs[8][2] = {}, css[8][2] = {};
    #pragma unroll
    for (int mi = 0; mi < 4; mi++) {
        #pragma unroll
        for (int half = 0; half < 2; half++) {
            int r = r0 + wm + mi * 16 + l4 + half * 8;
            int seg = 0;
            #pragma unroll
            for (int s = 0; s < NS; s++) seg += (r >= so[s]);
            #pragma unroll
            for (int ni = 0; ni < 8; ni++) {
                int c = c0 + wn + ni * 8 + 2 * lm4;
                float2 z2 = *(const float2*)&g_z[seg * C + c];
                float v0 = acc[mi][ni][half * 2 + 0] + z2.x;
                float v1 = acc[mi][ni][half * 2 + 1] + z2.y;
                *(float2*)&h[(size_t)r * C + c] = make_float2(v0, v1);
                cs[ni][0] += v0;  cs[ni][1] += v1;
                css[ni][0] = fmaf(v0, v0, css[ni][0]);
                css[ni][1] = fmaf(v1, v1, css[ni][1]);
            }
        }
    }
    #pragma unroll
    for (int ni = 0; ni < 8; ni++)
        #pragma unroll
        for (int j = 0; j < 2; j++)
            #pragma unroll
            for (int off = 4; off < 32; off <<= 1) {
                cs[ni][j]  += __shfl_xor_sync(0xffffffff, cs[ni][j],  off);
                css[ni][j] += __shfl_xor_sync(0xffffffff, css[ni][j], off);
            }
    if (l4 == 0) {
        #pragma unroll
        for (int ni = 0; ni < 8; ni++) {
            int c = wn + ni * 8 + 2 * lm4;          // local col in [0,128)
            atomicAdd(&shbn[c],     cs[ni][0]);
            atomicAdd(&shbn[c + 1], cs[ni][1]);
            atomicAdd(&shbn[128 + c],     css[ni][0]);
            atomicAdd(&shbn[128 + c + 1], css[ni][1]);
        }
    }
    __syncthreads();
    atomicAdd(&g_bn[c0 + tid], shbn[tid]);
    atomicAdd(&g_bn[C + c0 + tid], shbn[128 + tid]);
}

// ---------------- K7: out = relu(h*scale + shift); BN finalize fused ------
__global__ void k_apply(float* __restrict__ h,
                        const float* __restrict__ gamma,
                        const float* __restrict__ beta) {
    __shared__ float ssc[2 * C];
    int t = threadIdx.x;
    {
        float mu = g_bn[t] * (1.f / NP);
        float var = g_bn[C + t] * (1.f / NP) - mu * mu;
        float sc = gamma[t] * rsqrtf(var + 1e-5f);
        ssc[t] = sc;
        ssc[t + C] = beta[t] - mu * sc;
    }
    __syncthreads();
    size_t total = (size_t)NP * C / 4;
    for (size_t p = (size_t)blockIdx.x * 256 + t; p < total; p += (size_t)gridDim.x * 256) {
        float4 v = __ldcs(&((float4*)h)[p]);
        int cb = (int)((p * 4) & (C - 1));
        v.x = fmaxf(fmaf(v.x, ssc[cb + 0], ssc[C + cb + 0]), 0.f);
        v.y = fmaxf(fmaf(v.y, ssc[cb + 1], ssc[C + cb + 1]), 0.f);
        v.z = fmaxf(fmaf(v.z, ssc[cb + 2], ssc[C + cb + 2]), 0.f);
        v.w = fmaxf(fmaf(v.w, ssc[cb + 3], ssc[C + cb + 3]), 0.f);
        __stcs(&((float4*)h)[p], v);
    }
}

extern "C" void kernel_launch(void* const* d_in, const int* in_sizes, int n_in,
                              void* d_out, int out_size) {
    const float* x     = (const float*)d_in[0];
    const int*   o     = (const int*)d_in[1];
    const float* W1    = (const float*)d_in[2];
    const float* b1    = (const float*)d_in[3];
    const float* W2    = (const float*)d_in[4];
    const float* b2    = (const float*)d_in[5];
    const float* gamma = (const float*)d_in[6];
    const float* beta  = (const float*)d_in[7];
    float* h = (float*)d_out;

    static bool attr_done = false;
    if (!attr_done) {
        cudaFuncSetAttribute(k_mm, cudaFuncAttributeMaxDynamicSharedMemorySize, 65536);
        attr_done = true;
    }

    k_segsum<<<NS * 32, 256>>>(x, o);
    k_wt<<<dim3(8, 8, 3), dim3(32, 8)>>>(W1, W2);
    k_mlp1<<<NS * 32, 256>>>(o, b2);
    k_mlp2<<<NS * 32, 256>>>(b1);
    dim3 g(C / BN, NP / BM);
    k_mm<<<g, 128, 65536>>>(x, o, h);
    k_apply<<<4096, 256>>>(h, gamma, beta);
}

// round 9
// speedup vs baseline: 1.1109x; 1.1109x over previous
#include <cuda_runtime.h>
#include <cuda_fp16.h>
#include <cstdint>

#define NP 131072
#define NS 16
#define C  256

// ------------------------------- scratch ----------------------------------
__device__ __half g_wh[C * C];         // g_wh[n*C+k] = (half)W1[k*C+n]  (W1a^T fp16)
__device__ float g_w2t[C * C];         // W2^T
__device__ float g_w1bt[C * C];        // W1b^T
__device__ float g_part[NS * 32 * C];  // per-(seg,sub) partial sums
__device__ float g_y[NS * C];
__device__ float g_z[NS * C];
__device__ float g_bn[2 * C];

// ------------------------------- helpers ----------------------------------
__device__ __forceinline__ uint32_t s2u(const void* p) {
    uint32_t a;
    asm("{ .reg .u64 t; cvta.to.shared.u64 t, %1; cvt.u32.u64 %0, t; }" : "=r"(a) : "l"(p));
    return a;
}
__device__ __forceinline__ void cpa16(uint32_t dst, const void* src) {
    asm volatile("cp.async.cg.shared.global [%0], [%1], 16;" :: "r"(dst), "l"(src));
}
__device__ __forceinline__ uint32_t h2pack(float lo, float hi) {
    uint32_t u;
    asm("cvt.rn.f16x2.f32 %0, %1, %2;" : "=r"(u) : "f"(hi), "f"(lo));
    return u;
}

// ---------------- K2: ragged segment partial sums (no atomics) -------------
__global__ void k_segsum(const float* __restrict__ x, const int* __restrict__ o) {
    int seg = blockIdx.x >> 5;
    int sub = blockIdx.x & 31;
    int t = threadIdx.x;
    int start = seg ? o[seg - 1] : 0;
    int end = o[seg];
    float acc = 0.f;
    #pragma unroll 4
    for (int r = start + sub; r < end; r += 32)
        acc += x[(size_t)r * C + t];
    g_part[(size_t)blockIdx.x * C + t] = acc;
}

// ---------------- K2b: weight transposes; block (0,0,0) zeroes g_bn -------
__global__ void k_wt(const float* __restrict__ W1, const float* __restrict__ W2) {
    __shared__ float tl[32][33];
    int k0 = blockIdx.x * 32, n0 = blockIdx.y * 32;
    int which = blockIdx.z;
    int tx = threadIdx.x, ty = threadIdx.y;
    if (blockIdx.x == 0 && blockIdx.y == 0 && which == 0) {
        int t = ty * 32 + tx;
        g_bn[t] = 0.f;
        g_bn[t + 256] = 0.f;
    }
    const float* src = (which == 0) ? &W1[(size_t)k0 * C + n0]
                     : (which == 1) ? &W2[(size_t)k0 * C + n0]
                                    : &W1[(size_t)(C + k0) * C + n0];
    #pragma unroll
    for (int i = 0; i < 32; i += 8)
        tl[ty + i][tx] = src[(size_t)(ty + i) * C + tx];
    __syncthreads();
    #pragma unroll
    for (int i = 0; i < 32; i += 8) {
        float v = tl[tx][ty + i];
        if (which == 0)
            g_wh[(size_t)(n0 + ty + i) * C + k0 + tx] = __float2half_rn(v);
        else if (which == 1)
            g_w2t[(size_t)(n0 + ty + i) * C + k0 + tx] = v;
        else
            g_w1bt[(size_t)(n0 + ty + i) * C + k0 + tx] = v;
    }
}

// ---------------- K3a: y = relu(means @ W2 + b2), coalesced W2^T ----------
__global__ __launch_bounds__(256) void k_mlp1(const int* __restrict__ o,
                                              const float* __restrict__ b2) {
    __shared__ float m[C];
    int seg = blockIdx.x >> 5;
    int cb = blockIdx.x & 31;
    int t = threadIdx.x, w = t >> 5, lane = t & 31;
    int start = seg ? o[seg - 1] : 0;
    float inv = 1.f / (float)(o[seg] - start);
    float s = 0.f;
    #pragma unroll
    for (int sub = 0; sub < 32; sub++)
        s += g_part[(size_t)(seg * 32 + sub) * C + t];
    m[t] = s * inv;
    __syncthreads();
    int c = cb * 8 + w;
    const float* wr = &g_w2t[(size_t)c * C];
    float acc = 0.f;
    #pragma unroll
    for (int j = 0; j < 8; j++) {
        int k = lane + 32 * j;
        acc = fmaf(m[k], wr[k], acc);
    }
    #pragma unroll
    for (int off = 16; off; off >>= 1) acc += __shfl_xor_sync(0xffffffffu, acc, off);
    if (lane == 0) g_y[seg * C + c] = fmaxf(acc + b2[c], 0.f);
}

// ---------------- K3b: z = y @ W1b + b1, coalesced W1b^T -------------------
__global__ __launch_bounds__(256) void k_mlp2(const float* __restrict__ b1) {
    __shared__ float y[C];
    int seg = blockIdx.x >> 5;
    int cb = blockIdx.x & 31;
    int t = threadIdx.x, w = t >> 5, lane = t & 31;
    y[t] = g_y[seg * C + t];
    __syncthreads();
    int c = cb * 8 + w;
    const float* wr = &g_w1bt[(size_t)c * C];
    float acc = 0.f;
    #pragma unroll
    for (int j = 0; j < 8; j++) {
        int k = lane + 32 * j;
        acc = fmaf(y[k], wr[k], acc);
    }
    #pragma unroll
    for (int off = 16; off; off >>= 1) acc += __shfl_xor_sync(0xffffffffu, acc, off);
    if (lane == 0) g_z[seg * C + c] = acc + b1[c];
}

// ---------------- K4: fp16 mma.sync m16n8k16 GEMM --------------------------
// 128x128 block tile, BK=32, 8 warps (2m x 4n), warp tile 64x32, 2-stage.
// A: fp32 smem, 128 rows x 32 floats, SW128 XOR swizzle (per-stage 16KB).
// B: fp16 smem, 128 n-rows x 32 fp16 padded to 20 words/row (per-stage 10KB).
#define BM 128
#define BN 128
#define B_RS 20                       // B row stride in 4B words
#define A_BYTES 16384
#define B_BYTES (128 * B_RS * 4)      // 10240
#define SM_TOT (2 * (A_BYTES + B_BYTES))

__device__ __forceinline__ int sidx(int r, int k) {
    return r * 32 + (k ^ ((r & 7) * 4));
}

__global__ __launch_bounds__(256, 2) void k_mm(const float* __restrict__ x,
                                               const int* __restrict__ o,
                                               float* __restrict__ h) {
    extern __shared__ __align__(128) float smem[];
    __shared__ int so[NS];
    __shared__ float shbn[512];

    uint32_t sb = s2u(smem);
    int tid = threadIdx.x;
    int w = tid >> 5, lane = tid & 31;
    int l4 = lane >> 2, lm4 = lane & 3;
    int wm = (w & 1) * 64;
    int wn = (w >> 1) * 32;
    int r0 = blockIdx.y * BM;
    int c0 = blockIdx.x * BN;

    if (tid < NS) so[tid] = o[tid];
    shbn[tid] = 0.f;
    shbn[tid + 256] = 0.f;

    // stage tile kt -> buffer kt&1
    auto stage = [&](int kt) {
        int buf = kt & 1;
        const float* xs = x + (size_t)r0 * C + kt * 32;
        const __half* ws = g_wh + c0 * C + kt * 32;
        uint32_t ab = sb + buf * A_BYTES;
        uint32_t bb = sb + 2 * A_BYTES + buf * B_BYTES;
        #pragma unroll
        for (int i = 0; i < 4; i++) {            // A: 1024 chunks of 16B
            int cid = tid + i * 256;
            int row = cid >> 3, c16 = cid & 7;
            uint32_t off = row * 128 + ((c16 * 16) ^ ((row & 7) * 16));
            cpa16(ab + off, xs + (size_t)row * C + c16 * 4);
        }
        #pragma unroll
        for (int i = 0; i < 2; i++) {            // B: 512 chunks of 16B (8 fp16)
            int cid = tid + i * 256;
            int n = cid >> 2, c16 = cid & 3;
            cpa16(bb + n * (B_RS * 4) + c16 * 16, ws + (size_t)n * C + c16 * 8);
        }
        asm volatile("cp.async.commit_group;" ::: "memory");
    };

    float acc[4][4][4] = {};    // [mi][ni][frag]
    stage(0);

    for (int kt = 0; kt < 8; kt++) {
        if (kt < 7) {
            stage(kt + 1);
            asm volatile("cp.async.wait_group 1;" ::: "memory");
        } else {
            asm volatile("cp.async.wait_group 0;" ::: "memory");
        }
        __syncthreads();

        const float* A = smem + (kt & 1) * (A_BYTES / 4);
        const uint32_t* B = (const uint32_t*)(smem + 2 * (A_BYTES / 4)) + (kt & 1) * (B_BYTES / 4);

        #pragma unroll
        for (int ks = 0; ks < 2; ks++) {         // two k16 steps per BK=32
            int kb = ks * 16 + 2 * lm4;          // fp32/fp16 element k-offset
            uint32_t af[4][4];
            uint32_t bf[4][2];
            #pragma unroll
            for (int mi = 0; mi < 4; mi++) {
                int m0 = wm + mi * 16 + l4;
                float2 v0 = *(const float2*)&A[sidx(m0,     kb)];
                float2 v1 = *(const float2*)&A[sidx(m0 + 8, kb)];
                float2 v2 = *(const float2*)&A[sidx(m0,     kb + 8)];
                float2 v3 = *(const float2*)&A[sidx(m0 + 8, kb + 8)];
                af[mi][0] = h2pack(v0.x, v0.y);
                af[mi][1] = h2pack(v1.x, v1.y);
                af[mi][2] = h2pack(v2.x, v2.y);
                af[mi][3] = h2pack(v3.x, v3.y);
            }
            #pragma unroll
            for (int ni = 0; ni < 4; ni++) {
                int n = wn + ni * 8 + l4;
                bf[ni][0] = B[n * B_RS + ks * 8 + lm4];       // (k=2lm4, 2lm4+1)
                bf[ni][1] = B[n * B_RS + ks * 8 + lm4 + 4];   // (k+8, k+9)
            }
            #pragma unroll
            for (int mi = 0; mi < 4; mi++)
                #pragma unroll
                for (int ni = 0; ni < 4; ni++)
                    asm volatile(
                        "mma.sync.aligned.m16n8k16.row.col.f32.f16.f16.f32 "
                        "{%0,%1,%2,%3},{%4,%5,%6,%7},{%8,%9},{%0,%1,%2,%3};"
                        : "+f"(acc[mi][ni][0]), "+f"(acc[mi][ni][1]),
                          "+f"(acc[mi][ni][2]), "+f"(acc[mi][ni][3])
                        : "r"(af[mi][0]), "r"(af[mi][1]),
                          "r"(af[mi][2]), "r"(af[mi][3]),
                          "r"(bf[ni][0]), "r"(bf[ni][1]));
        }
        __syncthreads();
    }

    // ---- epilogue: + z[seg], write h, fused BN partial sums ----
    float cs[4][2] = {}, css[4][2] = {};
    #pragma unroll
    for (int mi = 0; mi < 4; mi++) {
        #pragma unroll
        for (int half = 0; half < 2; half++) {
            int r = r0 + wm + mi * 16 + l4 + half * 8;
            int seg = 0;
            #pragma unroll
            for (int s = 0; s < NS; s++) seg += (r >= so[s]);
            #pragma unroll
            for (int ni = 0; ni < 4; ni++) {
                int c = c0 + wn + ni * 8 + 2 * lm4;
                float2 z2 = *(const float2*)&g_z[seg * C + c];
                float v0 = acc[mi][ni][half * 2 + 0] + z2.x;
                float v1 = acc[mi][ni][half * 2 + 1] + z2.y;
                *(float2*)&h[(size_t)r * C + c] = make_float2(v0, v1);
                cs[ni][0] += v0;  cs[ni][1] += v1;
                css[ni][0] = fmaf(v0, v0, css[ni][0]);
                css[ni][1] = fmaf(v1, v1, css[ni][1]);
            }
        }
    }
    #pragma unroll
    for (int ni = 0; ni < 4; ni++)
        #pragma unroll
        for (int j = 0; j < 2; j++)
            #pragma unroll
            for (int off = 4; off < 32; off <<= 1) {
                cs[ni][j]  += __shfl_xor_sync(0xffffffff, cs[ni][j],  off);
                css[ni][j] += __shfl_xor_sync(0xffffffff, css[ni][j], off);
            }
    if (l4 == 0) {
        #pragma unroll
        for (int ni = 0; ni < 4; ni++) {
            int c = wn + ni * 8 + 2 * lm4;
            atomicAdd(&shbn[c],     cs[ni][0]);
            atomicAdd(&shbn[c + 1], cs[ni][1]);
            atomicAdd(&shbn[256 + c],     css[ni][0]);
            atomicAdd(&shbn[256 + c + 1], css[ni][1]);
        }
    }
    __syncthreads();
    atomicAdd(&g_bn[c0 + tid], shbn[tid]);
    atomicAdd(&g_bn[C + c0 + tid], shbn[256 + tid]);
}

// ---------------- K7: out = relu(h*scale + shift); BN finalize fused ------
__global__ void k_apply(float* __restrict__ h,
                        const float* __restrict__ gamma,
                        const float* __restrict__ beta) {
    __shared__ float ssc[2 * C];
    int t = threadIdx.x;
    {
        float mu = g_bn[t] * (1.f / NP);
        float var = g_bn[C + t] * (1.f / NP) - mu * mu;
        float sc = gamma[t] * rsqrtf(var + 1e-5f);
        ssc[t] = sc;
        ssc[t + C] = beta[t] - mu * sc;
    }
    __syncthreads();
    size_t total = (size_t)NP * C / 4;
    for (size_t p = (size_t)blockIdx.x * 256 + t; p < total; p += (size_t)gridDim.x * 256) {
        float4 v = __ldcs(&((float4*)h)[p]);
        int cb = (int)((p * 4) & (C - 1));
        v.x = fmaxf(fmaf(v.x, ssc[cb + 0], ssc[C + cb + 0]), 0.f);
        v.y = fmaxf(fmaf(v.y, ssc[cb + 1], ssc[C + cb + 1]), 0.f);
        v.z = fmaxf(fmaf(v.z, ssc[cb + 2], ssc[C + cb + 2]), 0.f);
        v.w = fmaxf(fmaf(v.w, ssc[cb + 3], ssc[C + cb + 3]), 0.f);
        __stcs(&((float4*)h)[p], v);
    }
}

extern "C" void kernel_launch(void* const* d_in, const int* in_sizes, int n_in,
                              void* d_out, int out_size) {
    const float* x     = (const float*)d_in[0];
    const int*   o     = (const int*)d_in[1];
    const float* W1    = (const float*)d_in[2];
    const float* b1    = (const float*)d_in[3];
    const float* W2    = (const float*)d_in[4];
    const float* b2    = (const float*)d_in[5];
    const float* gamma = (const float*)d_in[6];
    const float* beta  = (const float*)d_in[7];
    float* h = (float*)d_out;

    static bool attr_done = false;
    if (!attr_done) {
        cudaFuncSetAttribute(k_mm, cudaFuncAttributeMaxDynamicSharedMemorySize, SM_TOT);
        attr_done = true;
    }

    k_segsum<<<NS * 32, 256>>>(x, o);
    k_wt<<<dim3(8, 8, 3), dim3(32, 8)>>>(W1, W2);
    k_mlp1<<<NS * 32, 256>>>(o, b2);
    k_mlp2<<<NS * 32, 256>>>(b1);
    dim3 g(C / BN, NP / BM);
    k_mm<<<g, 256, SM_TOT>>>(x, o, h);
    k_apply<<<4096, 256>>>(h, gamma, beta);
}

// round 10
// speedup vs baseline: 1.4214x; 1.2795x over previous
#include <cuda_runtime.h>
#include <cuda_fp16.h>
#include <cstdint>

#define NP 131072
#define NS 16
#define C  256

// ------------------------------- scratch ----------------------------------
__device__ __half g_xh[(size_t)NP * C]; // fp16 copy of x (64 MiB)
__device__ __half g_wh[C * C];          // g_wh[n*C+k] = (half)W1[k*C+n]
__device__ float g_w2t[C * C];          // W2^T
__device__ float g_w1bt[C * C];         // W1b^T
__device__ float g_part[NS * 64 * C];   // per-(seg,stream) partial sums
__device__ float g_y[NS * C];
__device__ float g_z[NS * C];
__device__ float g_bn[2 * C];

// ------------------------------- helpers ----------------------------------
__device__ __forceinline__ uint32_t s2u(const void* p) {
    uint32_t a;
    asm("{ .reg .u64 t; cvta.to.shared.u64 t, %1; cvt.u32.u64 %0, t; }" : "=r"(a) : "l"(p));
    return a;
}
__device__ __forceinline__ void cpa16(uint32_t dst, const void* src) {
    asm volatile("cp.async.cg.shared.global [%0], [%1], 16;" :: "r"(dst), "l"(src));
}
__device__ __forceinline__ uint32_t h2pack(float lo, float hi) {
    uint32_t u;
    asm("cvt.rn.f16x2.f32 %0, %1, %2;" : "=r"(u) : "f"(hi), "f"(lo));
    return u;
}
__device__ __forceinline__ void ldm4(uint32_t* r, uint32_t addr) {
    asm volatile("ldmatrix.sync.aligned.m8n8.x4.shared.b16 {%0,%1,%2,%3}, [%4];"
                 : "=r"(r[0]), "=r"(r[1]), "=r"(r[2]), "=r"(r[3]) : "r"(addr));
}

// ---------------- K2: ragged segment partial sums + fp16 convert ----------
// 512 blocks (32/seg); thread t: channel pair 2*(t&127), row-stream (sub*2 + t>>7).
__global__ void k_segsum(const float* __restrict__ x, const int* __restrict__ o) {
    int seg = blockIdx.x >> 5;
    int sub = blockIdx.x & 31;
    int t = threadIdx.x;
    int tc = t & 127;
    int stream = sub * 2 + (t >> 7);
    int start = seg ? o[seg - 1] : 0;
    int end = o[seg];
    float a0 = 0.f, a1 = 0.f;
    for (int r = start + stream; r < end; r += 64) {
        float2 v = *(const float2*)&x[(size_t)r * C + 2 * tc];
        a0 += v.x; a1 += v.y;
        *(uint32_t*)&g_xh[(size_t)r * C + 2 * tc] = h2pack(v.x, v.y);
    }
    *(float2*)&g_part[(size_t)(seg * 64 + stream) * C + 2 * tc] = make_float2(a0, a1);
}

// ---------------- K2b: weight transposes; block (0,0,0) zeroes g_bn -------
__global__ void k_wt(const float* __restrict__ W1, const float* __restrict__ W2) {
    __shared__ float tl[32][33];
    int k0 = blockIdx.x * 32, n0 = blockIdx.y * 32;
    int which = blockIdx.z;
    int tx = threadIdx.x, ty = threadIdx.y;
    if (blockIdx.x == 0 && blockIdx.y == 0 && which == 0) {
        int t = ty * 32 + tx;
        g_bn[t] = 0.f;
        g_bn[t + 256] = 0.f;
    }
    const float* src = (which == 0) ? &W1[(size_t)k0 * C + n0]
                     : (which == 1) ? &W2[(size_t)k0 * C + n0]
                                    : &W1[(size_t)(C + k0) * C + n0];
    #pragma unroll
    for (int i = 0; i < 32; i += 8)
        tl[ty + i][tx] = src[(size_t)(ty + i) * C + tx];
    __syncthreads();
    #pragma unroll
    for (int i = 0; i < 32; i += 8) {
        float v = tl[tx][ty + i];
        if (which == 0)
            g_wh[(size_t)(n0 + ty + i) * C + k0 + tx] = __float2half_rn(v);
        else if (which == 1)
            g_w2t[(size_t)(n0 + ty + i) * C + k0 + tx] = v;
        else
            g_w1bt[(size_t)(n0 + ty + i) * C + k0 + tx] = v;
    }
}

// ---------------- K3a: y = relu(means @ W2 + b2) ---------------------------
__global__ __launch_bounds__(256) void k_mlp1(const int* __restrict__ o,
                                              const float* __restrict__ b2) {
    __shared__ float m[C];
    int seg = blockIdx.x >> 5;
    int cb = blockIdx.x & 31;
    int t = threadIdx.x, w = t >> 5, lane = t & 31;
    int start = seg ? o[seg - 1] : 0;
    float inv = 1.f / (float)(o[seg] - start);
    float s = 0.f;
    #pragma unroll
    for (int sub = 0; sub < 64; sub++)
        s += g_part[(size_t)(seg * 64 + sub) * C + t];
    m[t] = s * inv;
    __syncthreads();
    int c = cb * 8 + w;
    const float* wr = &g_w2t[(size_t)c * C];
    float acc = 0.f;
    #pragma unroll
    for (int j = 0; j < 8; j++) {
        int k = lane + 32 * j;
        acc = fmaf(m[k], wr[k], acc);
    }
    #pragma unroll
    for (int off = 16; off; off >>= 1) acc += __shfl_xor_sync(0xffffffffu, acc, off);
    if (lane == 0) g_y[seg * C + c] = fmaxf(acc + b2[c], 0.f);
}

// ---------------- K3b: z = y @ W1b + b1 ------------------------------------
__global__ __launch_bounds__(256) void k_mlp2(const float* __restrict__ b1) {
    __shared__ float y[C];
    int seg = blockIdx.x >> 5;
    int cb = blockIdx.x & 31;
    int t = threadIdx.x, w = t >> 5, lane = t & 31;
    y[t] = g_y[seg * C + t];
    __syncthreads();
    int c = cb * 8 + w;
    const float* wr = &g_w1bt[(size_t)c * C];
    float acc = 0.f;
    #pragma unroll
    for (int j = 0; j < 8; j++) {
        int k = lane + 32 * j;
        acc = fmaf(y[k], wr[k], acc);
    }
    #pragma unroll
    for (int off = 16; off; off >>= 1) acc += __shfl_xor_sync(0xffffffffu, acc, off);
    if (lane == 0) g_z[seg * C + c] = acc + b1[c];
}

// ---------------- K4: fp16 mma m16n8k16 + ldmatrix, 2-stage cp.async ------
// 128x128 block, BK=32, 8 warps (2m x 4n), warp tile 64x32.
// A,B fp16 in smem: 128 rows x 32 halfs, padded row stride 20 words (80B).
// 20r mod 32 distinct for r in [0,8) -> ldmatrix conflict-free.
#define BM 128
#define BN 128
#define T_BYTES 10240                  // 128 * 80
#define STAGE_BYTES (2 * T_BYTES)      // A + B
#define SM_TOT (2 * STAGE_BYTES)       // 40960

__global__ __launch_bounds__(256, 2) void k_mm(const int* __restrict__ o,
                                               float* __restrict__ h) {
    extern __shared__ __align__(128) float smem[];
    __shared__ int so[NS];
    __shared__ float shbn[512];

    uint32_t sb = s2u(smem);
    int tid = threadIdx.x;
    int w = tid >> 5, lane = tid & 31;
    int l4 = lane >> 2, lm4 = lane & 3;
    int j8 = lane >> 3, lr = lane & 7;     // ldmatrix addressing
    int wm = (w & 1) * 64;
    int wn = (w >> 1) * 32;
    int r0 = blockIdx.y * BM;
    int c0 = blockIdx.x * BN;

    if (tid < NS) so[tid] = o[tid];
    shbn[tid] = 0.f;
    shbn[tid + 256] = 0.f;

    // stage tile kt -> buffer kt&1 (A then B; 512 16B-chunks each)
    auto stage = [&](int kt) {
        int buf = kt & 1;
        const __half* xs = g_xh + (size_t)r0 * C + kt * 32;
        const __half* ws = g_wh + (size_t)c0 * C + kt * 32;
        uint32_t ab = sb + buf * STAGE_BYTES;
        uint32_t bb = ab + T_BYTES;
        #pragma unroll
        for (int i = 0; i < 2; i++) {
            int cid = tid + i * 256;
            int row = cid >> 2, c = cid & 3;
            cpa16(ab + row * 80 + c * 16, xs + (size_t)row * C + c * 8);
            cpa16(bb + row * 80 + c * 16, ws + (size_t)row * C + c * 8);
        }
        asm volatile("cp.async.commit_group;" ::: "memory");
    };

    float acc[4][4][4] = {};
    stage(0);

    for (int kt = 0; kt < 8; kt++) {
        if (kt < 7) {
            stage(kt + 1);
            asm volatile("cp.async.wait_group 1;" ::: "memory");
        } else {
            asm volatile("cp.async.wait_group 0;" ::: "memory");
        }
        __syncthreads();

        uint32_t abase = sb + (kt & 1) * STAGE_BYTES;
        uint32_t bbase = abase + T_BYTES;

        #pragma unroll
        for (int ks = 0; ks < 2; ks++) {
            uint32_t af[4][4];
            uint32_t bf[4][2];
            // A: 4 ldmatrix.x4; tiles (r0k0),(r8k0),(r0k8),(r8k8)
            #pragma unroll
            for (int mi = 0; mi < 4; mi++) {
                int row = wm + mi * 16 + (j8 & 1) * 8 + lr;
                ldm4(af[mi], abase + row * 80 + ks * 32 + (j8 >> 1) * 16);
            }
            // B: 2 ldmatrix.x4; tiles (nA,k0),(nA,k8),(nB,k0),(nB,k8)
            #pragma unroll
            for (int p = 0; p < 2; p++) {
                int n = wn + (2 * p + (j8 >> 1)) * 8 + lr;
                uint32_t bw[4];
                ldm4(bw, bbase + n * 80 + ks * 32 + (j8 & 1) * 16);
                bf[2 * p][0] = bw[0];  bf[2 * p][1] = bw[1];
                bf[2 * p + 1][0] = bw[2];  bf[2 * p + 1][1] = bw[3];
            }
            #pragma unroll
            for (int mi = 0; mi < 4; mi++)
                #pragma unroll
                for (int ni = 0; ni < 4; ni++)
                    asm volatile(
                        "mma.sync.aligned.m16n8k16.row.col.f32.f16.f16.f32 "
                        "{%0,%1,%2,%3},{%4,%5,%6,%7},{%8,%9},{%0,%1,%2,%3};"
                        : "+f"(acc[mi][ni][0]), "+f"(acc[mi][ni][1]),
                          "+f"(acc[mi][ni][2]), "+f"(acc[mi][ni][3])
                        : "r"(af[mi][0]), "r"(af[mi][1]),
                          "r"(af[mi][2]), "r"(af[mi][3]),
                          "r"(bf[ni][0]), "r"(bf[ni][1]));
        }
        __syncthreads();
    }

    // ---- epilogue: + z[seg], write h, fused BN partial sums ----
    float cs[4][2] = {}, css[4][2] = {};
    #pragma unroll
    for (int mi = 0; mi < 4; mi++) {
        #pragma unroll
        for (int half = 0; half < 2; half++) {
            int r = r0 + wm + mi * 16 + l4 + half * 8;
            int seg = 0;
            #pragma unroll
            for (int s = 0; s < NS; s++) seg += (r >= so[s]);
            #pragma unroll
            for (int ni = 0; ni < 4; ni++) {
                int c = c0 + wn + ni * 8 + 2 * lm4;
                float2 z2 = *(const float2*)&g_z[seg * C + c];
                float v0 = acc[mi][ni][half * 2 + 0] + z2.x;
                float v1 = acc[mi][ni][half * 2 + 1] + z2.y;
                *(float2*)&h[(size_t)r * C + c] = make_float2(v0, v1);
                cs[ni][0] += v0;  cs[ni][1] += v1;
                css[ni][0] = fmaf(v0, v0, css[ni][0]);
                css[ni][1] = fmaf(v1, v1, css[ni][1]);
            }
        }
    }
    #pragma unroll
    for (int ni = 0; ni < 4; ni++)
        #pragma unroll
        for (int j = 0; j < 2; j++)
            #pragma unroll
            for (int off = 4; off < 32; off <<= 1) {
                cs[ni][j]  += __shfl_xor_sync(0xffffffff, cs[ni][j],  off);
                css[ni][j] += __shfl_xor_sync(0xffffffff, css[ni][j], off);
            }
    if (l4 == 0) {
        #pragma unroll
        for (int ni = 0; ni < 4; ni++) {
            int c = wn + ni * 8 + 2 * lm4;
            atomicAdd(&shbn[c],     cs[ni][0]);
            atomicAdd(&shbn[c + 1], cs[ni][1]);
            atomicAdd(&shbn[256 + c],     css[ni][0]);
            atomicAdd(&shbn[256 + c + 1], css[ni][1]);
        }
    }
    __syncthreads();
    atomicAdd(&g_bn[c0 + tid], shbn[tid]);
    atomicAdd(&g_bn[C + c0 + tid], shbn[256 + tid]);
}

// ---------------- K7: out = relu(h*scale + shift); BN finalize fused ------
__global__ void k_apply(float* __restrict__ h,
                        const float* __restrict__ gamma,
                        const float* __restrict__ beta) {
    __shared__ float ssc[2 * C];
    int t = threadIdx.x;
    {
        float mu = g_bn[t] * (1.f / NP);
        float var = g_bn[C + t] * (1.f / NP) - mu * mu;
        float sc = gamma[t] * rsqrtf(var + 1e-5f);
        ssc[t] = sc;
        ssc[t + C] = beta[t] - mu * sc;
    }
    __syncthreads();
    size_t total = (size_t)NP * C / 4;
    for (size_t p = (size_t)blockIdx.x * 256 + t; p < total; p += (size_t)gridDim.x * 256) {
        float4 v = __ldcs(&((float4*)h)[p]);
        int cb = (int)((p * 4) & (C - 1));
        v.x = fmaxf(fmaf(v.x, ssc[cb + 0], ssc[C + cb + 0]), 0.f);
        v.y = fmaxf(fmaf(v.y, ssc[cb + 1], ssc[C + cb + 1]), 0.f);
        v.z = fmaxf(fmaf(v.z, ssc[cb + 2], ssc[C + cb + 2]), 0.f);
        v.w = fmaxf(fmaf(v.w, ssc[cb + 3], ssc[C + cb + 3]), 0.f);
        __stcs(&((float4*)h)[p], v);
    }
}

extern "C" void kernel_launch(void* const* d_in, const int* in_sizes, int n_in,
                              void* d_out, int out_size) {
    const float* x     = (const float*)d_in[0];
    const int*   o     = (const int*)d_in[1];
    const float* W1    = (const float*)d_in[2];
    const float* b1    = (const float*)d_in[3];
    const float* W2    = (const float*)d_in[4];
    const float* b2    = (const float*)d_in[5];
    const float* gamma = (const float*)d_in[6];
    const float* beta  = (const float*)d_in[7];
    float* h = (float*)d_out;

    static bool attr_done = false;
    if (!attr_done) {
        cudaFuncSetAttribute(k_mm, cudaFuncAttributeMaxDynamicSharedMemorySize, SM_TOT);
        attr_done = true;
    }

    k_segsum<<<NS * 32, 256>>>(x, o);
    k_wt<<<dim3(8, 8, 3), dim3(32, 8)>>>(W1, W2);
    k_mlp1<<<NS * 32, 256>>>(o, b2);
    k_mlp2<<<NS * 32, 256>>>(b1);
    dim3 g(C / BN, NP / BM);
    k_mm<<<g, 256, SM_TOT>>>(o, h);
    k_apply<<<4096, 256>>>(h, gamma, beta);
}